// round 1
// baseline (speedup 1.0000x reference)
#include <cuda_runtime.h>

#define NP 768
#define CC 128
#define NSPLIT 2
#define NPER (NP / NSPLIT)   // 384
#define TILE 128
#define L2E 1.4426950408889634f

// Quartic polynomial coefficients for the layer-3 linear outputs:
// La3[c](d,u,v) = sum_j g_P[0][c][j] * mono_j,  Lb3 likewise with g_P[1].
__device__ float g_P[2][CC][35];
// Partial online-softmax stats per (m, split, {max,denom,num0,num1,num2}, c)
__device__ float g_part[NP][NSPLIT][5][CC];

// ---------------------------------------------------------------------------
// Precompute: expand the 3 bilinear layers into per-channel quartic
// polynomials in (d, u, v). One CTA, 128 threads (thread = channel).
// Monomial enumeration (35): for a=0..4, b=0..4-a, c=0..4-a-b  ->  d^a u^b v^c
// ---------------------------------------------------------------------------
__global__ void precompute_kernel(
    const float* __restrict__ Wa1, const float* __restrict__ ba1,
    const float* __restrict__ Wb1, const float* __restrict__ bb1,
    const float* __restrict__ Wa2, const float* __restrict__ ba2,
    const float* __restrict__ Wb2, const float* __restrict__ bb2,
    const float* __restrict__ Wa3, const float* __restrict__ ba3,
    const float* __restrict__ Wb3, const float* __restrict__ bb3)
{
    __shared__ float sA[CC][4], sB[CC][4];
    __shared__ float sE[CC][35];
    __shared__ int sLUT[125];
    const int t = threadIdx.x;

    if (t == 0) {
        int j = 0;
        for (int a = 0; a <= 4; ++a)
            for (int b = 0; b <= 4 - a; ++b)
                for (int c = 0; c <= 4 - a - b; ++c)
                    sLUT[a * 25 + b * 5 + c] = j++;
    }
    // Layer-1 homogeneous vectors over g = (d, u, v, 1)
    sA[t][0] = Wa1[3*t];   sA[t][1] = Wa1[3*t+1];
    sA[t][2] = Wa1[3*t+2]; sA[t][3] = ba1[t];
    sB[t][0] = Wb1[3*t];   sB[t][1] = Wb1[3*t+1];
    sB[t][2] = Wb1[3*t+2]; sB[t][3] = bb1[t];
    __syncthreads();

    // Layer-2 linears as quadratic forms: 10 coefficients over pairs
    // (0,0),(0,1),(0,2),(0,3),(1,1),(1,2),(1,3),(2,2),(2,3),(3,3)
    float qa[10], qb[10];
    #pragma unroll
    for (int p = 0; p < 10; ++p) { qa[p] = 0.f; qb[p] = 0.f; }
    for (int k = 0; k < CC; ++k) {
        float wa = Wa2[t*CC + k], wb = Wb2[t*CC + k];
        float A0 = sA[k][0], A1 = sA[k][1], A2 = sA[k][2], A3 = sA[k][3];
        float B0 = sB[k][0], B1 = sB[k][1], B2 = sB[k][2], B3 = sB[k][3];
        float v[10];
        v[0] = A0*B0;
        v[1] = A0*B1 + A1*B0;
        v[2] = A0*B2 + A2*B0;
        v[3] = A0*B3 + A3*B0;
        v[4] = A1*B1;
        v[5] = A1*B2 + A2*B1;
        v[6] = A1*B3 + A3*B1;
        v[7] = A2*B2;
        v[8] = A2*B3 + A3*B2;
        v[9] = A3*B3;
        #pragma unroll
        for (int p = 0; p < 10; ++p) {
            qa[p] = fmaf(wa, v[p], qa[p]);
            qb[p] = fmaf(wb, v[p], qb[p]);
        }
    }
    qa[9] += ba2[t];  // bias sits on the (3,3) == constant monomial
    qb[9] += bb2[t];

    // h2[t] = Qa(g) * Qb(g): expand product of two quadratics -> quartic (35)
    #pragma unroll
    for (int j = 0; j < 35; ++j) sE[t][j] = 0.f;
    {
        // exponent keys (a*25+b*5+c) of the 10 quadratic pair-monomials
        const int pk[10] = {50, 30, 26, 25, 10, 6, 5, 2, 1, 0};
        #pragma unroll
        for (int p = 0; p < 10; ++p) {
            float va = qa[p];
            #pragma unroll
            for (int q = 0; q < 10; ++q)
                sE[t][sLUT[pk[p] + pk[q]]] += va * qb[q];
        }
    }
    __syncthreads();

    // Layer-3 linears: P = W3 @ E (+ bias on constant monomial j=0)
    float pa[35], pb[35];
    #pragma unroll
    for (int j = 0; j < 35; ++j) { pa[j] = 0.f; pb[j] = 0.f; }
    for (int k = 0; k < CC; ++k) {
        float wa = Wa3[t*CC + k], wb = Wb3[t*CC + k];
        #pragma unroll
        for (int j = 0; j < 35; ++j) {
            float ev = sE[k][j];
            pa[j] = fmaf(wa, ev, pa[j]);
            pb[j] = fmaf(wb, ev, pb[j]);
        }
    }
    pa[0] += ba3[t];
    pb[0] += bb3[t];
    #pragma unroll
    for (int j = 0; j < 35; ++j) {
        g_P[0][t][j] = pa[j];
        g_P[1][t][j] = pb[j];
    }
}

// ---------------------------------------------------------------------------
// Main: one CTA per (m, n-split). Thread = channel. Folds u-powers into the
// coefficients (15 monomials in (d,v) remain), online softmax over n.
// ---------------------------------------------------------------------------
__global__ void __launch_bounds__(128, 8) fps_main_kernel(const float* __restrict__ x)
{
    __shared__ float sm[TILE][20];  // [0..14] monomials, [15..17] x[n], pad
    const int m = blockIdx.x;
    const int s = blockIdx.y;
    const int t = threadIdx.x;

    const float xm0 = x[3*m], xm1 = x[3*m+1], xm2 = x[3*m+2];
    const float um2 = xm0*xm0 + xm1*xm1 + xm2*xm2;
    const float u = sqrtf(um2);
    float up[5];
    up[0] = 1.f; up[1] = u; up[2] = u*u; up[3] = up[2]*u; up[4] = up[2]*up[2];

    // Fold u^b into coefficients: 35 (a,b,c) -> 15 (a,c) monomials
    const int JB[35] = {0,0,0,0,0, 1,1,1,1, 2,2,2, 3,3, 4,
                        0,0,0,0, 1,1,1, 2,2, 3,
                        0,0,0, 1,1, 2,
                        0,0, 1, 0};
    const int JF[35] = {0,1,2,3,4, 0,1,2,3, 0,1,2, 0,1, 0,
                        5,6,7,8, 5,6,7, 5,6, 5,
                        9,10,11, 9,10, 9,
                        12,13, 12, 14};
    float paf[15], pbf[15];
    #pragma unroll
    for (int f = 0; f < 15; ++f) { paf[f] = 0.f; pbf[f] = 0.f; }
    #pragma unroll
    for (int j = 0; j < 35; ++j) {
        float ub = up[JB[j]];
        paf[JF[j]] = fmaf(g_P[0][t][j], ub, paf[JF[j]]);
        pbf[JF[j]] = fmaf(g_P[1][t][j], ub, pbf[JF[j]]);
    }

    float Mx = -1e30f, D = 0.f, a0 = 0.f, a1 = 0.f, a2 = 0.f;

    for (int tile = 0; tile < NPER / TILE; ++tile) {
        const int n = s * NPER + tile * TILE + t;
        // phase 1: monomials of (d, v) for this n into shared
        float xn0 = x[3*n], xn1 = x[3*n+1], xn2 = x[3*n+2];
        float vn2 = xn0*xn0 + xn1*xn1 + xn2*xn2;
        float v  = sqrtf(vn2);
        float d2 = um2 + vn2 - 2.f*(xm0*xn0 + xm1*xn1 + xm2*xn2);
        float d  = sqrtf(fmaxf(d2, 0.f));
        float v2 = v*v,  v3 = v2*v,  v4 = v2*v2;
        float dd2 = d*d, dd3 = dd2*d, dd4 = dd2*dd2;
        __syncthreads();  // previous tile's readers done
        sm[t][0]  = 1.f;  sm[t][1]  = v;      sm[t][2]  = v2;
        sm[t][3]  = v3;   sm[t][4]  = v4;
        sm[t][5]  = d;    sm[t][6]  = d*v;    sm[t][7]  = d*v2;  sm[t][8] = d*v3;
        sm[t][9]  = dd2;  sm[t][10] = dd2*v;  sm[t][11] = dd2*v2;
        sm[t][12] = dd3;  sm[t][13] = dd3*v;
        sm[t][14] = dd4;
        sm[t][15] = xn0;  sm[t][16] = xn1;    sm[t][17] = xn2;
        __syncthreads();

        // phase 2: per-channel polynomial eval + online softmax accumulate
        #pragma unroll 4
        for (int nn = 0; nn < TILE; ++nn) {
            float la = paf[0], lb = pbf[0];
            #pragma unroll
            for (int j = 1; j < 15; ++j) {
                float mv = sm[nn][j];
                la = fmaf(paf[j], mv, la);
                lb = fmaf(pbf[j], mv, lb);
            }
            float h = la * lb;
            if (h > Mx) {
                float r = exp2f((Mx - h) * L2E);
                D *= r; a0 *= r; a1 *= r; a2 *= r;
                Mx = h;
            }
            float e = exp2f((h - Mx) * L2E);
            D += e;
            a0 = fmaf(e, sm[nn][15], a0);
            a1 = fmaf(e, sm[nn][16], a1);
            a2 = fmaf(e, sm[nn][17], a2);
        }
    }

    g_part[m][s][0][t] = Mx;
    g_part[m][s][1][t] = D;
    g_part[m][s][2][t] = a0;
    g_part[m][s][3][t] = a1;
    g_part[m][s][4][t] = a2;
}

// ---------------------------------------------------------------------------
// Reduce: merge n-splits (max-rescaled), sum over m, apply Wf, emit 9 floats.
// Deterministic (fixed-order tree reduction, no atomics).
// ---------------------------------------------------------------------------
__global__ void reduce_kernel(const float* __restrict__ x,
                              const float* __restrict__ Wf,
                              float* __restrict__ out)
{
    __shared__ float red[6][CC];
    const int c = threadIdx.x;
    float s0 = 0.f, s1 = 0.f, s2 = 0.f;
    for (int m = 0; m < NP; ++m) {
        float Ma = g_part[m][0][0][c], Da = g_part[m][0][1][c];
        float A0 = g_part[m][0][2][c], A1 = g_part[m][0][3][c], A2 = g_part[m][0][4][c];
        float Mb = g_part[m][1][0][c], Db = g_part[m][1][1][c];
        float B0 = g_part[m][1][2][c], B1 = g_part[m][1][3][c], B2 = g_part[m][1][4][c];
        float Mm = fmaxf(Ma, Mb);
        float ra = exp2f((Ma - Mm) * L2E);
        float rb = exp2f((Mb - Mm) * L2E);
        float inv = 1.f / fmaf(Da, ra, Db * rb);
        s0 += fmaf(A0, ra, B0 * rb) * inv;
        s1 += fmaf(A1, ra, B1 * rb) * inv;
        s2 += fmaf(A2, ra, B2 * rb) * inv;
    }
    float w0 = Wf[c], w1 = Wf[CC + c];
    red[0][c] = w0 * s0; red[1][c] = w0 * s1; red[2][c] = w0 * s2;
    red[3][c] = w1 * s0; red[4][c] = w1 * s1; red[5][c] = w1 * s2;
    __syncthreads();
    for (int off = 64; off > 0; off >>= 1) {
        if (c < off) {
            #pragma unroll
            for (int q = 0; q < 6; ++q) red[q][c] += red[q][c + off];
        }
        __syncthreads();
    }
    if (c < 3) out[c] = x[c];           // row 0 = x[0, 0, :]
    if (c == 0) {
        #pragma unroll
        for (int q = 0; q < 6; ++q) out[3 + q] = red[q][0];
    }
}

extern "C" void kernel_launch(void* const* d_in, const int* in_sizes, int n_in,
                              void* d_out, int out_size)
{
    const float* x   = (const float*)d_in[0];
    const float* Wa1 = (const float*)d_in[1];
    const float* ba1 = (const float*)d_in[2];
    const float* Wb1 = (const float*)d_in[3];
    const float* bb1 = (const float*)d_in[4];
    const float* Wa2 = (const float*)d_in[5];
    const float* ba2 = (const float*)d_in[6];
    const float* Wb2 = (const float*)d_in[7];
    const float* bb2 = (const float*)d_in[8];
    const float* Wa3 = (const float*)d_in[9];
    const float* ba3 = (const float*)d_in[10];
    const float* Wb3 = (const float*)d_in[11];
    const float* bb3 = (const float*)d_in[12];
    const float* Wf  = (const float*)d_in[13];

    precompute_kernel<<<1, 128>>>(Wa1, ba1, Wb1, bb1,
                                  Wa2, ba2, Wb2, bb2,
                                  Wa3, ba3, Wb3, bb3);
    dim3 grid(NP, NSPLIT);
    fps_main_kernel<<<grid, 128>>>(x);
    reduce_kernel<<<1, 128>>>(x, Wf, (float*)d_out);
}

// round 2
// speedup vs baseline: 2.3718x; 2.3718x over previous
#include <cuda_runtime.h>

#define NP 768
#define CC 128
#define NSPLIT 6
#define TILE 128          // NPER == TILE: one tile per CTA
#define L2E 1.4426950408889634f
#define RBLK 48           // reduceA blocks (16 m each)

// Quartic polynomial coefficients, TRANSPOSED for coalesced reads: [o][monomial j][channel]
__device__ float g_P[2][35][CC];
// Partial online-softmax stats per (m, split, {max,denom,num0,num1,num2}, c)
__device__ float g_part[NP][NSPLIT][5][CC];
// Per-block partial sums over m of softmax-normalized aggregates: [blk][3][c]
__device__ float g_red[RBLK][3][CC];

// ---------------- f32x2 packed helpers (sm_103a) ----------------
__device__ __forceinline__ unsigned long long pack2(float lo, float hi) {
    unsigned long long r;
    asm("mov.b64 %0, {%1,%2};" : "=l"(r) : "f"(lo), "f"(hi));
    return r;
}
__device__ __forceinline__ void unpack2(float& lo, float& hi, unsigned long long v) {
    asm("mov.b64 {%0,%1}, %2;" : "=f"(lo), "=f"(hi) : "l"(v));
}
__device__ __forceinline__ unsigned long long ffma2(unsigned long long a,
                                                    unsigned long long b,
                                                    unsigned long long c) {
    unsigned long long d;
    asm("fma.rn.f32x2 %0, %1, %2, %3;" : "=l"(d) : "l"(a), "l"(b), "l"(c));
    return d;
}
__device__ __forceinline__ unsigned long long fmul2(unsigned long long a,
                                                    unsigned long long b) {
    unsigned long long d;
    asm("mul.rn.f32x2 %0, %1, %2;" : "=l"(d) : "l"(a), "l"(b));
    return d;
}

// ---------------------------------------------------------------------------
// Precompute: expand the 3 bilinear layers into per-channel quartic
// polynomials in (d, u, v). One CTA, 256 threads.
// Monomials (35): a=0..4 (d), b=0..4-a (u), c=0..4-a-b (v), lexicographic.
// ---------------------------------------------------------------------------
__global__ void __launch_bounds__(256) precompute_kernel(
    const float* __restrict__ Wa1, const float* __restrict__ ba1,
    const float* __restrict__ Wb1, const float* __restrict__ bb1,
    const float* __restrict__ Wa2, const float* __restrict__ ba2,
    const float* __restrict__ Wb2, const float* __restrict__ bb2,
    const float* __restrict__ Wa3, const float* __restrict__ ba3,
    const float* __restrict__ Wb3, const float* __restrict__ bb3)
{
    __shared__ float sV[CC][10];          // layer-1 pair-product quadratics per k
    __shared__ float sE[CC][35];          // per-channel quartic of h2
    __shared__ float sWa[CC][17], sWb[CC][17];  // staged weight tiles (padded)
    __shared__ int sLUT[125];
    const int t = threadIdx.x;
    const int c = t & 127;
    const int half = t >> 7;

    if (t == 0) {
        int j = 0;
        for (int a = 0; a <= 4; ++a)
            for (int b = 0; b <= 4 - a; ++b)
                for (int cc = 0; cc <= 4 - a - b; ++cc)
                    sLUT[a * 25 + b * 5 + cc] = j++;
    }
    if (half == 0) {
        // Layer-1 homogeneous vectors over g = (d, u, v, 1); expand pairwise
        // products into sV (quadratic form coefficients over pairs
        // (0,0),(0,1),(0,2),(0,3),(1,1),(1,2),(1,3),(2,2),(2,3),(3,3))
        float A0 = Wa1[3*c], A1 = Wa1[3*c+1], A2 = Wa1[3*c+2], A3 = ba1[c];
        float B0 = Wb1[3*c], B1 = Wb1[3*c+1], B2 = Wb1[3*c+2], B3 = bb1[c];
        sV[c][0] = A0*B0;
        sV[c][1] = A0*B1 + A1*B0;
        sV[c][2] = A0*B2 + A2*B0;
        sV[c][3] = A0*B3 + A3*B0;
        sV[c][4] = A1*B1;
        sV[c][5] = A1*B2 + A2*B1;
        sV[c][6] = A1*B3 + A3*B1;
        sV[c][7] = A2*B2;
        sV[c][8] = A2*B3 + A3*B2;
        sV[c][9] = A3*B3;
    }

    // ---- Layer 2: qa/qb = quadratic forms; stage W2 tiles coalesced ----
    float qa[10], qb[10];
    #pragma unroll
    for (int p = 0; p < 10; ++p) { qa[p] = 0.f; qb[p] = 0.f; }
    for (int k0 = 0; k0 < CC; k0 += 16) {
        __syncthreads();
        for (int i = t; i < CC * 16; i += 256) {
            int r = i >> 4, kk = i & 15;
            sWa[r][kk] = Wa2[r * CC + k0 + kk];
            sWb[r][kk] = Wb2[r * CC + k0 + kk];
        }
        __syncthreads();
        if (half == 0) {
            #pragma unroll 4
            for (int kk = 0; kk < 16; ++kk) {
                int k = k0 + kk;
                float wa = sWa[c][kk], wb = sWb[c][kk];
                #pragma unroll
                for (int p = 0; p < 10; ++p) {
                    float vv = sV[k][p];
                    qa[p] = fmaf(wa, vv, qa[p]);
                    qb[p] = fmaf(wb, vv, qb[p]);
                }
            }
        }
    }
    __syncthreads();
    if (half == 0) {
        qa[9] += ba2[c];   // bias = constant monomial
        qb[9] += bb2[c];
        // h2[c] = Qa * Qb -> quartic expansion (35 coefficients)
        #pragma unroll
        for (int j = 0; j < 35; ++j) sE[c][j] = 0.f;
        const int pk[10] = {50, 30, 26, 25, 10, 6, 5, 2, 1, 0};
        #pragma unroll
        for (int p = 0; p < 10; ++p) {
            float va = qa[p];
            #pragma unroll
            for (int q = 0; q < 10; ++q)
                sE[c][sLUT[pk[p] + pk[q]]] += va * qb[q];
        }
    }

    // ---- Layer 3: P = W3 @ E; j-range split across the two halves ----
    float pa[18], pb[18];
    #pragma unroll
    for (int j = 0; j < 18; ++j) { pa[j] = 0.f; pb[j] = 0.f; }
    for (int k0 = 0; k0 < CC; k0 += 16) {
        __syncthreads();
        for (int i = t; i < CC * 16; i += 256) {
            int r = i >> 4, kk = i & 15;
            sWa[r][kk] = Wa3[r * CC + k0 + kk];
            sWb[r][kk] = Wb3[r * CC + k0 + kk];
        }
        __syncthreads();
        #pragma unroll 2
        for (int kk = 0; kk < 16; ++kk) {
            float wa = sWa[c][kk], wb = sWb[c][kk];
            const float* e = &sE[k0 + kk][0];
            if (half == 0) {
                #pragma unroll
                for (int j = 0; j < 18; ++j) {
                    pa[j] = fmaf(wa, e[j], pa[j]);
                    pb[j] = fmaf(wb, e[j], pb[j]);
                }
            } else {
                #pragma unroll
                for (int j = 0; j < 17; ++j) {
                    pa[j] = fmaf(wa, e[18 + j], pa[j]);
                    pb[j] = fmaf(wb, e[18 + j], pb[j]);
                }
            }
        }
    }
    if (half == 0) {
        pa[0] += ba3[c];
        pb[0] += bb3[c];
        #pragma unroll
        for (int j = 0; j < 18; ++j) {
            g_P[0][j][c] = pa[j];
            g_P[1][j][c] = pb[j];
        }
    } else {
        #pragma unroll
        for (int j = 0; j < 17; ++j) {
            g_P[0][18 + j][c] = pa[j];
            g_P[1][18 + j][c] = pb[j];
        }
    }
}

// ---------------------------------------------------------------------------
// Main: one CTA per (m, n-split of 128). Thread = channel.
// Folds u-powers into coefficients (15 monomials in (d,v)); evaluates two
// quartics per n with packed f32x2 FMA, two n's at a time; online softmax.
// ---------------------------------------------------------------------------
__global__ void __launch_bounds__(128) fps_main_kernel(const float* __restrict__ x)
{
    __shared__ float smA[14][TILE];   // monomials f1..f14, transposed
    __shared__ float smX[3][TILE];    // x[n] components
    const int m = blockIdx.x;
    const int s = blockIdx.y;
    const int t = threadIdx.x;

    const float xm0 = x[3*m], xm1 = x[3*m+1], xm2 = x[3*m+2];
    const float um2 = fmaf(xm0, xm0, fmaf(xm1, xm1, xm2 * xm2));
    const float u = sqrtf(um2);
    float up[5];
    up[0] = 1.f; up[1] = u; up[2] = um2; up[3] = um2 * u; up[4] = um2 * um2;

    // ---- phase 1: monomials of (d, v) for this CTA's 128 n's ----
    {
        const int n = s * TILE + t;
        float xn0 = x[3*n], xn1 = x[3*n+1], xn2 = x[3*n+2];
        float vn2 = fmaf(xn0, xn0, fmaf(xn1, xn1, xn2 * xn2));
        float v = sqrtf(vn2);
        float d2 = um2 + vn2 - 2.f * fmaf(xm0, xn0, fmaf(xm1, xn1, xm2 * xn2));
        float d = sqrtf(fmaxf(d2, 0.f));
        float v2 = v * v, v3 = v2 * v, v4 = v2 * v2;
        float dd2 = d * d, dd3 = dd2 * d, dd4 = dd2 * dd2;
        smA[0][t]  = v;      smA[1][t]  = v2;     smA[2][t]  = v3;  smA[3][t] = v4;
        smA[4][t]  = d;      smA[5][t]  = d*v;    smA[6][t]  = d*v2;
        smA[7][t]  = d*v3;
        smA[8][t]  = dd2;    smA[9][t]  = dd2*v;  smA[10][t] = dd2*v2;
        smA[11][t] = dd3;    smA[12][t] = dd3*v;
        smA[13][t] = dd4;
        smX[0][t] = xn0; smX[1][t] = xn1; smX[2][t] = xn2;
    }

    // ---- fold u^b into coefficients: 35 (a,b,c) -> 15 (a,c) ----
    const int JB[35] = {0,0,0,0,0, 1,1,1,1, 2,2,2, 3,3, 4,
                        0,0,0,0, 1,1,1, 2,2, 3,
                        0,0,0, 1,1, 2,
                        0,0, 1, 0};
    const int JF[35] = {0,1,2,3,4, 0,1,2,3, 0,1,2, 0,1, 0,
                        5,6,7,8, 5,6,7, 5,6, 5,
                        9,10,11, 9,10, 9,
                        12,13, 12, 14};
    float paf[15], pbf[15];
    #pragma unroll
    for (int f = 0; f < 15; ++f) { paf[f] = 0.f; pbf[f] = 0.f; }
    #pragma unroll
    for (int j = 0; j < 35; ++j) {
        float ub = up[JB[j]];
        paf[JF[j]] = fmaf(g_P[0][j][t], ub, paf[JF[j]]);
        pbf[JF[j]] = fmaf(g_P[1][j][t], ub, pbf[JF[j]]);
    }
    unsigned long long paf2[15], pbf2[15];
    #pragma unroll
    for (int f = 0; f < 15; ++f) {
        paf2[f] = pack2(paf[f], paf[f]);
        pbf2[f] = pack2(pbf[f], pbf[f]);
    }
    __syncthreads();

    // ---- phase 2: packed poly eval + dual online softmax ----
    float Mx0 = -1e30f, D0 = 0.f, a00 = 0.f, a01 = 0.f, a02 = 0.f;
    float Mx1 = -1e30f, D1 = 0.f, a10 = 0.f, a11 = 0.f, a12 = 0.f;

    #pragma unroll 2
    for (int nn = 0; nn < TILE; nn += 2) {
        unsigned long long la = paf2[0], lb = pbf2[0];
        #pragma unroll
        for (int j = 1; j < 15; ++j) {
            unsigned long long mv =
                *(const unsigned long long*)&smA[j - 1][nn];
            la = ffma2(paf2[j], mv, la);
            lb = ffma2(pbf2[j], mv, lb);
        }
        unsigned long long h2 = fmul2(la, lb);
        float hlo, hhi;
        unpack2(hlo, hhi, h2);

        // set 0 (even n)
        if (hlo > Mx0) {
            float r = exp2f((Mx0 - hlo) * L2E);
            D0 *= r; a00 *= r; a01 *= r; a02 *= r;
            Mx0 = hlo;
        }
        float e0 = exp2f((hlo - Mx0) * L2E);
        D0 += e0;
        a00 = fmaf(e0, smX[0][nn], a00);
        a01 = fmaf(e0, smX[1][nn], a01);
        a02 = fmaf(e0, smX[2][nn], a02);

        // set 1 (odd n)
        if (hhi > Mx1) {
            float r = exp2f((Mx1 - hhi) * L2E);
            D1 *= r; a10 *= r; a11 *= r; a12 *= r;
            Mx1 = hhi;
        }
        float e1 = exp2f((hhi - Mx1) * L2E);
        D1 += e1;
        a10 = fmaf(e1, smX[0][nn + 1], a10);
        a11 = fmaf(e1, smX[1][nn + 1], a11);
        a12 = fmaf(e1, smX[2][nn + 1], a12);
    }

    // merge the two sets
    float Mx = fmaxf(Mx0, Mx1);
    float r0 = exp2f((Mx0 - Mx) * L2E);
    float r1 = exp2f((Mx1 - Mx) * L2E);
    g_part[m][s][0][t] = Mx;
    g_part[m][s][1][t] = fmaf(D0, r0, D1 * r1);
    g_part[m][s][2][t] = fmaf(a00, r0, a10 * r1);
    g_part[m][s][3][t] = fmaf(a01, r0, a11 * r1);
    g_part[m][s][4][t] = fmaf(a02, r0, a12 * r1);
}

// ---------------------------------------------------------------------------
// ReduceA: merge NSPLIT partials per m (max-rescaled), normalize, partial-sum
// over a 16-m block. grid=RBLK, block=128. Deterministic.
// ---------------------------------------------------------------------------
__global__ void __launch_bounds__(128) reduceA_kernel()
{
    const int c = threadIdx.x;
    const int m0 = blockIdx.x * (NP / RBLK);
    float s0 = 0.f, s1 = 0.f, s2 = 0.f;
    for (int m = m0; m < m0 + NP / RBLK; ++m) {
        float Mm = -1e30f;
        #pragma unroll
        for (int s = 0; s < NSPLIT; ++s)
            Mm = fmaxf(Mm, g_part[m][s][0][c]);
        float D = 0.f, A0 = 0.f, A1 = 0.f, A2 = 0.f;
        #pragma unroll
        for (int s = 0; s < NSPLIT; ++s) {
            float r = exp2f((g_part[m][s][0][c] - Mm) * L2E);
            D  = fmaf(g_part[m][s][1][c], r, D);
            A0 = fmaf(g_part[m][s][2][c], r, A0);
            A1 = fmaf(g_part[m][s][3][c], r, A1);
            A2 = fmaf(g_part[m][s][4][c], r, A2);
        }
        float inv = 1.f / D;
        s0 = fmaf(A0, inv, s0);
        s1 = fmaf(A1, inv, s1);
        s2 = fmaf(A2, inv, s2);
    }
    g_red[blockIdx.x][0][c] = s0;
    g_red[blockIdx.x][1][c] = s1;
    g_red[blockIdx.x][2][c] = s2;
}

// ---------------------------------------------------------------------------
// ReduceB: sum blocks, apply Wf, tree-reduce over channels, emit 9 floats.
// ---------------------------------------------------------------------------
__global__ void __launch_bounds__(128) reduceB_kernel(const float* __restrict__ x,
                                                      const float* __restrict__ Wf,
                                                      float* __restrict__ out)
{
    __shared__ float red[6][CC];
    const int c = threadIdx.x;
    float s0 = 0.f, s1 = 0.f, s2 = 0.f;
    #pragma unroll 4
    for (int b = 0; b < RBLK; ++b) {
        s0 += g_red[b][0][c];
        s1 += g_red[b][1][c];
        s2 += g_red[b][2][c];
    }
    float w0 = Wf[c], w1 = Wf[CC + c];
    red[0][c] = w0 * s0; red[1][c] = w0 * s1; red[2][c] = w0 * s2;
    red[3][c] = w1 * s0; red[4][c] = w1 * s1; red[5][c] = w1 * s2;
    __syncthreads();
    for (int off = 64; off > 0; off >>= 1) {
        if (c < off) {
            #pragma unroll
            for (int q = 0; q < 6; ++q) red[q][c] += red[q][c + off];
        }
        __syncthreads();
    }
    if (c < 3) out[c] = x[c];           // row 0 = x[0, 0, :]
    if (c == 0) {
        #pragma unroll
        for (int q = 0; q < 6; ++q) out[3 + q] = red[q][0];
    }
}

extern "C" void kernel_launch(void* const* d_in, const int* in_sizes, int n_in,
                              void* d_out, int out_size)
{
    const float* x   = (const float*)d_in[0];
    const float* Wa1 = (const float*)d_in[1];
    const float* ba1 = (const float*)d_in[2];
    const float* Wb1 = (const float*)d_in[3];
    const float* bb1 = (const float*)d_in[4];
    const float* Wa2 = (const float*)d_in[5];
    const float* ba2 = (const float*)d_in[6];
    const float* Wb2 = (const float*)d_in[7];
    const float* bb2 = (const float*)d_in[8];
    const float* Wa3 = (const float*)d_in[9];
    const float* ba3 = (const float*)d_in[10];
    const float* Wb3 = (const float*)d_in[11];
    const float* bb3 = (const float*)d_in[12];
    const float* Wf  = (const float*)d_in[13];

    precompute_kernel<<<1, 256>>>(Wa1, ba1, Wb1, bb1,
                                  Wa2, ba2, Wb2, bb2,
                                  Wa3, ba3, Wb3, bb3);
    dim3 grid(NP, NSPLIT);
    fps_main_kernel<<<grid, 128>>>(x);
    reduceA_kernel<<<RBLK, 128>>>();
    reduceB_kernel<<<1, 128>>>(x, Wf, (float*)d_out);
}

// round 5
// speedup vs baseline: 2.4696x; 1.0412x over previous
#include <cuda_runtime.h>

#define NP 768
#define CC 128
#define NSPLIT 6
#define TILE 128          // n's per CTA (one tile)
#define L2E 1.4426950408889634f
#define RBLK 48           // reduceA blocks (16 m each)

// Quartic polynomial coefficients (from precompute): [o][monomial j][channel]
__device__ float g_P[2][35][CC];
// Per-m folded coefficients, duplicated into float2 for direct f32x2 use.
// g_Pf[m][0] is pre-scaled by log2(e). Layout: [m][o][j(15)][c] float2.
__device__ float2 g_Pf[NP][2][15][CC];
// Partial online-softmax stats per (m, split, {max,denom,num0,num1,num2}, c)
__device__ float g_part[NP][NSPLIT][5][CC];
// Per-block partial sums over m of softmax-normalized aggregates: [q][blk][c]
__device__ float g_red[3][RBLK][CC];

// ---------------- f32x2 packed helpers (sm_103a) ----------------
typedef unsigned long long ull;
__device__ __forceinline__ ull pack2(float lo, float hi) {
    ull r;
    asm("mov.b64 %0, {%1,%2};" : "=l"(r) : "f"(lo), "f"(hi));
    return r;
}
__device__ __forceinline__ void unpack2(float& lo, float& hi, ull v) {
    asm("mov.b64 {%0,%1}, %2;" : "=f"(lo), "=f"(hi) : "l"(v));
}
__device__ __forceinline__ ull ffma2(ull a, ull b, ull c) {
    ull d;
    asm("fma.rn.f32x2 %0, %1, %2, %3;" : "=l"(d) : "l"(a), "l"(b), "l"(c));
    return d;
}
__device__ __forceinline__ ull fmul2(ull a, ull b) {
    ull d;
    asm("mul.rn.f32x2 %0, %1, %2;" : "=l"(d) : "l"(a), "l"(b));
    return d;
}
__device__ __forceinline__ ull fadd2(ull a, ull b) {
    ull d;
    asm("add.rn.f32x2 %0, %1, %2;" : "=l"(d) : "l"(a), "l"(b));
    return d;
}

// ---------------------------------------------------------------------------
// Precompute: expand the 3 bilinear layers into per-channel quartic
// polynomials in (d, u, v). One CTA, 256 threads.
// Monomials (35): a=0..4 (d), b=0..4-a (u), c=0..4-a-b (v), lexicographic.
// ---------------------------------------------------------------------------
__global__ void __launch_bounds__(256) precompute_kernel(
    const float* __restrict__ Wa1, const float* __restrict__ ba1,
    const float* __restrict__ Wb1, const float* __restrict__ bb1,
    const float* __restrict__ Wa2, const float* __restrict__ ba2,
    const float* __restrict__ Wb2, const float* __restrict__ bb2,
    const float* __restrict__ Wa3, const float* __restrict__ ba3,
    const float* __restrict__ Wb3, const float* __restrict__ bb3)
{
    __shared__ float sV[CC][10];
    __shared__ float sE[CC][35];
    __shared__ float sWa[CC][17], sWb[CC][17];
    __shared__ int sLUT[125];
    const int t = threadIdx.x;
    const int c = t & 127;
    const int half = t >> 7;

    if (t == 0) {
        int j = 0;
        for (int a = 0; a <= 4; ++a)
            for (int b = 0; b <= 4 - a; ++b)
                for (int cc = 0; cc <= 4 - a - b; ++cc)
                    sLUT[a * 25 + b * 5 + cc] = j++;
    }
    if (half == 0) {
        float A0 = Wa1[3*c], A1 = Wa1[3*c+1], A2 = Wa1[3*c+2], A3 = ba1[c];
        float B0 = Wb1[3*c], B1 = Wb1[3*c+1], B2 = Wb1[3*c+2], B3 = bb1[c];
        sV[c][0] = A0*B0;
        sV[c][1] = A0*B1 + A1*B0;
        sV[c][2] = A0*B2 + A2*B0;
        sV[c][3] = A0*B3 + A3*B0;
        sV[c][4] = A1*B1;
        sV[c][5] = A1*B2 + A2*B1;
        sV[c][6] = A1*B3 + A3*B1;
        sV[c][7] = A2*B2;
        sV[c][8] = A2*B3 + A3*B2;
        sV[c][9] = A3*B3;
    }

    float qa[10], qb[10];
    #pragma unroll
    for (int p = 0; p < 10; ++p) { qa[p] = 0.f; qb[p] = 0.f; }
    for (int k0 = 0; k0 < CC; k0 += 16) {
        __syncthreads();
        for (int i = t; i < CC * 16; i += 256) {
            int r = i >> 4, kk = i & 15;
            sWa[r][kk] = Wa2[r * CC + k0 + kk];
            sWb[r][kk] = Wb2[r * CC + k0 + kk];
        }
        __syncthreads();
        if (half == 0) {
            #pragma unroll 4
            for (int kk = 0; kk < 16; ++kk) {
                int k = k0 + kk;
                float wa = sWa[c][kk], wb = sWb[c][kk];
                #pragma unroll
                for (int p = 0; p < 10; ++p) {
                    float vv = sV[k][p];
                    qa[p] = fmaf(wa, vv, qa[p]);
                    qb[p] = fmaf(wb, vv, qb[p]);
                }
            }
        }
    }
    __syncthreads();
    if (half == 0) {
        qa[9] += ba2[c];
        qb[9] += bb2[c];
        #pragma unroll
        for (int j = 0; j < 35; ++j) sE[c][j] = 0.f;
        const int pk[10] = {50, 30, 26, 25, 10, 6, 5, 2, 1, 0};
        #pragma unroll
        for (int p = 0; p < 10; ++p) {
            float va = qa[p];
            #pragma unroll
            for (int q = 0; q < 10; ++q)
                sE[c][sLUT[pk[p] + pk[q]]] += va * qb[q];
        }
    }

    float pa[18], pb[18];
    #pragma unroll
    for (int j = 0; j < 18; ++j) { pa[j] = 0.f; pb[j] = 0.f; }
    for (int k0 = 0; k0 < CC; k0 += 16) {
        __syncthreads();
        for (int i = t; i < CC * 16; i += 256) {
            int r = i >> 4, kk = i & 15;
            sWa[r][kk] = Wa3[r * CC + k0 + kk];
            sWb[r][kk] = Wb3[r * CC + k0 + kk];
        }
        __syncthreads();
        #pragma unroll 2
        for (int kk = 0; kk < 16; ++kk) {
            float wa = sWa[c][kk], wb = sWb[c][kk];
            const float* e = &sE[k0 + kk][0];
            if (half == 0) {
                #pragma unroll
                for (int j = 0; j < 18; ++j) {
                    pa[j] = fmaf(wa, e[j], pa[j]);
                    pb[j] = fmaf(wb, e[j], pb[j]);
                }
            } else {
                #pragma unroll
                for (int j = 0; j < 17; ++j) {
                    pa[j] = fmaf(wa, e[18 + j], pa[j]);
                    pb[j] = fmaf(wb, e[18 + j], pb[j]);
                }
            }
        }
    }
    if (half == 0) {
        pa[0] += ba3[c];
        pb[0] += bb3[c];
        #pragma unroll
        for (int j = 0; j < 18; ++j) {
            g_P[0][j][c] = pa[j];
            g_P[1][j][c] = pb[j];
        }
    } else {
        #pragma unroll
        for (int j = 0; j < 17; ++j) {
            g_P[0][18 + j][c] = pa[j];
            g_P[1][18 + j][c] = pb[j];
        }
    }
}

// ---------------------------------------------------------------------------
// Fold: per m, collapse u^b into the coefficients: 35 (a,b,c) -> 15 (a,c).
// Output duplicated into float2; P_a pre-scaled by log2(e).
// grid(96), block(128): each CTA handles 8 consecutive m.
// ---------------------------------------------------------------------------
__global__ void __launch_bounds__(128) fold_kernel(const float* __restrict__ x)
{
    const int c = threadIdx.x;
    const int JB[35] = {0,0,0,0,0, 1,1,1,1, 2,2,2, 3,3, 4,
                        0,0,0,0, 1,1,1, 2,2, 3,
                        0,0,0, 1,1, 2,
                        0,0, 1, 0};
    const int JF[35] = {0,1,2,3,4, 0,1,2,3, 0,1,2, 0,1, 0,
                        5,6,7,8, 5,6,7, 5,6, 5,
                        9,10,11, 9,10, 9,
                        12,13, 12, 14};
    for (int mi = 0; mi < 8; ++mi) {
        const int m = blockIdx.x * 8 + mi;
        float xm0 = x[3*m], xm1 = x[3*m+1], xm2 = x[3*m+2];
        float um2 = fmaf(xm0, xm0, fmaf(xm1, xm1, xm2 * xm2));
        float u = sqrtf(um2);
        float up[5];
        up[0] = 1.f; up[1] = u; up[2] = um2; up[3] = um2 * u; up[4] = um2 * um2;
        float paf[15], pbf[15];
        #pragma unroll
        for (int f = 0; f < 15; ++f) { paf[f] = 0.f; pbf[f] = 0.f; }
        #pragma unroll
        for (int j = 0; j < 35; ++j) {
            float ub = up[JB[j]];
            paf[JF[j]] = fmaf(g_P[0][j][c], ub, paf[JF[j]]);
            pbf[JF[j]] = fmaf(g_P[1][j][c], ub, pbf[JF[j]]);
        }
        #pragma unroll
        for (int j = 0; j < 15; ++j) {
            float a = paf[j] * L2E;          // fold log2(e) into P_a
            g_Pf[m][0][j][c] = make_float2(a, a);
            g_Pf[m][1][j][c] = make_float2(pbf[j], pbf[j]);
        }
    }
}

// ---------------------------------------------------------------------------
// Main: one CTA per (m, n-split of 128). Thread = channel.
// Fully packed f32x2 path: poly eval, h, and softmax accumulation all handle
// two n's per iteration. h is in log2 units (exp2 directly).
// ---------------------------------------------------------------------------
__global__ void __launch_bounds__(128) fps_main_kernel(const float* __restrict__ x)
{
    // interleaved monomials: [pair nn][slot 0..13 (monomials 1..14), pad to 18][even/odd]
    __shared__ __align__(16) float smP[TILE/2][18][2];
    __shared__ __align__(16) float smX[3][TILE];
    const int m = blockIdx.x;
    const int s = blockIdx.y;
    const int t = threadIdx.x;

    const float xm0 = x[3*m], xm1 = x[3*m+1], xm2 = x[3*m+2];
    const float um2 = fmaf(xm0, xm0, fmaf(xm1, xm1, xm2 * xm2));

    // ---- phase 1: monomials of (d, v) for this CTA's 128 n's ----
    {
        const int n = s * TILE + t;
        float xn0 = x[3*n], xn1 = x[3*n+1], xn2 = x[3*n+2];
        float vn2 = fmaf(xn0, xn0, fmaf(xn1, xn1, xn2 * xn2));
        float v = sqrtf(vn2);
        float d2 = um2 + vn2 - 2.f * fmaf(xm0, xn0, fmaf(xm1, xn1, xm2 * xn2));
        float d = sqrtf(fmaxf(d2, 0.f));
        float v2 = v * v, v3 = v2 * v, v4 = v2 * v2;
        float dd2 = d * d, dd3 = dd2 * d, dd4 = dd2 * dd2;
        const int pr = t >> 1, ln = t & 1;
        smP[pr][0][ln]  = v;      smP[pr][1][ln]  = v2;
        smP[pr][2][ln]  = v3;     smP[pr][3][ln]  = v4;
        smP[pr][4][ln]  = d;      smP[pr][5][ln]  = d*v;
        smP[pr][6][ln]  = d*v2;   smP[pr][7][ln]  = d*v3;
        smP[pr][8][ln]  = dd2;    smP[pr][9][ln]  = dd2*v;
        smP[pr][10][ln] = dd2*v2; smP[pr][11][ln] = dd3;
        smP[pr][12][ln] = dd3*v;  smP[pr][13][ln] = dd4;
        smX[0][t] = xn0; smX[1][t] = xn1; smX[2][t] = xn2;
    }

    // ---- load pre-folded duplicated coefficients (coalesced LDG.64) ----
    ull paf2[15], pbf2[15];
    #pragma unroll
    for (int j = 0; j < 15; ++j) {
        paf2[j] = *(const ull*)&g_Pf[m][0][j][t];
        pbf2[j] = *(const ull*)&g_Pf[m][1][j][t];
    }
    __syncthreads();

    // ---- phase 2: packed poly eval + dual online softmax ----
    float Mx0 = -1e30f, Mx1 = -1e30f;
    ull D2 = pack2(0.f, 0.f);
    ull A0 = D2, A1 = D2, A2 = D2;

    #pragma unroll 2
    for (int nn = 0; nn < TILE / 2; ++nn) {
        ull la = paf2[0], lb = pbf2[0];
        #pragma unroll
        for (int sj = 0; sj < 14; sj += 2) {
            ulonglong2 q = *(const ulonglong2*)&smP[nn][sj][0];
            la = ffma2(paf2[sj + 1], q.x, la);
            lb = ffma2(pbf2[sj + 1], q.x, lb);
            la = ffma2(paf2[sj + 2], q.y, la);
            lb = ffma2(pbf2[sj + 2], q.y, lb);
        }
        ull h2 = fmul2(la, lb);           // log2 units
        float hlo, hhi;
        unpack2(hlo, hhi, h2);

        if (hlo > Mx0 || hhi > Mx1) {     // rare rescale
            float nM0 = fmaxf(Mx0, hlo), nM1 = fmaxf(Mx1, hhi);
            float r0 = exp2f(Mx0 - nM0), r1 = exp2f(Mx1 - nM1);
            Mx0 = nM0; Mx1 = nM1;
            ull r2 = pack2(r0, r1);
            D2 = fmul2(D2, r2);
            A0 = fmul2(A0, r2); A1 = fmul2(A1, r2); A2 = fmul2(A2, r2);
        }
        float e0 = exp2f(hlo - Mx0), e1 = exp2f(hhi - Mx1);
        ull e2 = pack2(e0, e1);
        D2 = fadd2(D2, e2);
        A0 = ffma2(e2, *(const ull*)&smX[0][2*nn], A0);
        A1 = ffma2(e2, *(const ull*)&smX[1][2*nn], A1);
        A2 = ffma2(e2, *(const ull*)&smX[2][2*nn], A2);
    }

    // merge even/odd lanes
    float D0, D1, a00, a10, a01, a11, a02, a12;
    unpack2(D0, D1, D2);
    unpack2(a00, a10, A0);
    unpack2(a01, a11, A1);
    unpack2(a02, a12, A2);
    float Mx = fmaxf(Mx0, Mx1);
    float r0 = exp2f(Mx0 - Mx);
    float r1 = exp2f(Mx1 - Mx);
    g_part[m][s][0][t] = Mx;              // log2 units
    g_part[m][s][1][t] = fmaf(D0, r0, D1 * r1);
    g_part[m][s][2][t] = fmaf(a00, r0, a10 * r1);
    g_part[m][s][3][t] = fmaf(a01, r0, a11 * r1);
    g_part[m][s][4][t] = fmaf(a02, r0, a12 * r1);
}

// ---------------------------------------------------------------------------
// ReduceA: merge NSPLIT partials per m (max-rescaled, log2 units), normalize,
// partial-sum over a 16-m block. grid=RBLK, block=128. Deterministic.
// ---------------------------------------------------------------------------
__global__ void __launch_bounds__(128) reduceA_kernel()
{
    const int c = threadIdx.x;
    const int m0 = blockIdx.x * (NP / RBLK);
    float s0 = 0.f, s1 = 0.f, s2 = 0.f;
    #pragma unroll 2
    for (int m = m0; m < m0 + NP / RBLK; ++m) {
        float Mm = -1e30f;
        #pragma unroll
        for (int s = 0; s < NSPLIT; ++s)
            Mm = fmaxf(Mm, g_part[m][s][0][c]);
        float D = 0.f, A0 = 0.f, A1 = 0.f, A2 = 0.f;
        #pragma unroll
        for (int s = 0; s < NSPLIT; ++s) {
            float r = exp2f(g_part[m][s][0][c] - Mm);
            D  = fmaf(g_part[m][s][1][c], r, D);
            A0 = fmaf(g_part[m][s][2][c], r, A0);
            A1 = fmaf(g_part[m][s][3][c], r, A1);
            A2 = fmaf(g_part[m][s][4][c], r, A2);
        }
        float inv = 1.f / D;
        s0 = fmaf(A0, inv, s0);
        s1 = fmaf(A1, inv, s1);
        s2 = fmaf(A2, inv, s2);
    }
    g_red[0][blockIdx.x][c] = s0;
    g_red[1][blockIdx.x][c] = s1;
    g_red[2][blockIdx.x][c] = s2;
}

// ---------------------------------------------------------------------------
// ReduceB: sum blocks (high-MLP unrolled), apply Wf, tree-reduce, emit 9.
// ---------------------------------------------------------------------------
__global__ void __launch_bounds__(128) reduceB_kernel(const float* __restrict__ x,
                                                      const float* __restrict__ Wf,
                                                      float* __restrict__ out)
{
    __shared__ float red[6][CC];
    const int c = threadIdx.x;
    float s0 = 0.f, s1 = 0.f, s2 = 0.f;
    #pragma unroll
    for (int b = 0; b < RBLK; ++b) {
        s0 += g_red[0][b][c];
        s1 += g_red[1][b][c];
        s2 += g_red[2][b][c];
    }
    float w0 = Wf[c], w1 = Wf[CC + c];
    red[0][c] = w0 * s0; red[1][c] = w0 * s1; red[2][c] = w0 * s2;
    red[3][c] = w1 * s0; red[4][c] = w1 * s1; red[5][c] = w1 * s2;
    __syncthreads();
    for (int off = 64; off > 0; off >>= 1) {
        if (c < off) {
            #pragma unroll
            for (int q = 0; q < 6; ++q) red[q][c] += red[q][c + off];
        }
        __syncthreads();
    }
    if (c < 3) out[c] = x[c];             // row 0 = x[0, 0, :]
    if (c == 0) {
        #pragma unroll
        for (int q = 0; q < 6; ++q) out[3 + q] = red[q][0];
    }
}

extern "C" void kernel_launch(void* const* d_in, const int* in_sizes, int n_in,
                              void* d_out, int out_size)
{
    const float* x   = (const float*)d_in[0];
    const float* Wa1 = (const float*)d_in[1];
    const float* ba1 = (const float*)d_in[2];
    const float* Wb1 = (const float*)d_in[3];
    const float* bb1 = (const float*)d_in[4];
    const float* Wa2 = (const float*)d_in[5];
    const float* ba2 = (const float*)d_in[6];
    const float* Wb2 = (const float*)d_in[7];
    const float* bb2 = (const float*)d_in[8];
    const float* Wa3 = (const float*)d_in[9];
    const float* ba3 = (const float*)d_in[10];
    const float* Wb3 = (const float*)d_in[11];
    const float* bb3 = (const float*)d_in[12];
    const float* Wf  = (const float*)d_in[13];

    precompute_kernel<<<1, 256>>>(Wa1, ba1, Wb1, bb1,
                                  Wa2, ba2, Wb2, bb2,
                                  Wa3, ba3, Wb3, bb3);
    fold_kernel<<<NP / 8, 128>>>(x);
    dim3 grid(NP, NSPLIT);
    fps_main_kernel<<<grid, 128>>>(x);
    reduceA_kernel<<<RBLK, 128>>>();
    reduceB_kernel<<<1, 128>>>(x, Wf, (float*)d_out);
}

// round 7
// speedup vs baseline: 2.5768x; 1.0434x over previous
#include <cuda_runtime.h>

#define NP 768
#define CC 128
#define TILE 128
#define NTILES (NP / TILE)    // 6 n-tiles per CTA
#define L2E 1.4426950408889634f
#define RBLK 48               // reduceB blocks (16 m each)

// Quartic polynomial coefficients (from precompute): [o][monomial j][channel]
__device__ float g_P[2][35][CC];
// Normalized per-(m,c) softmax aggregates: [q in 0..2][m][c]
__device__ float g_norm[3][NP][CC];
// Per-block partial results after Wf: [blk][q in 0..5]
__device__ float g_fin[RBLK][6];

// ---------------- f32x2 packed helpers (sm_103a) ----------------
typedef unsigned long long ull;
__device__ __forceinline__ ull pack2(float lo, float hi) {
    ull r;
    asm("mov.b64 %0, {%1,%2};" : "=l"(r) : "f"(lo), "f"(hi));
    return r;
}
__device__ __forceinline__ void unpack2(float& lo, float& hi, ull v) {
    asm("mov.b64 {%0,%1}, %2;" : "=f"(lo), "=f"(hi) : "l"(v));
}
__device__ __forceinline__ ull ffma2(ull a, ull b, ull c) {
    ull d;
    asm("fma.rn.f32x2 %0, %1, %2, %3;" : "=l"(d) : "l"(a), "l"(b), "l"(c));
    return d;
}
__device__ __forceinline__ ull fmul2(ull a, ull b) {
    ull d;
    asm("mul.rn.f32x2 %0, %1, %2;" : "=l"(d) : "l"(a), "l"(b));
    return d;
}
__device__ __forceinline__ ull fadd2(ull a, ull b) {
    ull d;
    asm("add.rn.f32x2 %0, %1, %2;" : "=l"(d) : "l"(a), "l"(b));
    return d;
}

// ---------------------------------------------------------------------------
// Precompute: expand the 3 bilinear layers into per-channel quartic
// polynomials in (d, u, v). One CTA, 256 threads.
// Monomials (35): a=0..4 (d), b=0..4-a (u), c=0..4-a-b (v), lexicographic.
// ---------------------------------------------------------------------------
__global__ void __launch_bounds__(256) precompute_kernel(
    const float* __restrict__ Wa1, const float* __restrict__ ba1,
    const float* __restrict__ Wb1, const float* __restrict__ bb1,
    const float* __restrict__ Wa2, const float* __restrict__ ba2,
    const float* __restrict__ Wb2, const float* __restrict__ bb2,
    const float* __restrict__ Wa3, const float* __restrict__ ba3,
    const float* __restrict__ Wb3, const float* __restrict__ bb3)
{
    __shared__ float sV[CC][10];
    __shared__ float sE[CC][35];
    __shared__ float sWa[CC][17], sWb[CC][17];
    __shared__ int sLUT[125];
    const int t = threadIdx.x;
    const int c = t & 127;
    const int half = t >> 7;

    if (t == 0) {
        int j = 0;
        for (int a = 0; a <= 4; ++a)
            for (int b = 0; b <= 4 - a; ++b)
                for (int cc = 0; cc <= 4 - a - b; ++cc)
                    sLUT[a * 25 + b * 5 + cc] = j++;
    }
    if (half == 0) {
        float A0 = Wa1[3*c], A1 = Wa1[3*c+1], A2 = Wa1[3*c+2], A3 = ba1[c];
        float B0 = Wb1[3*c], B1 = Wb1[3*c+1], B2 = Wb1[3*c+2], B3 = bb1[c];
        sV[c][0] = A0*B0;
        sV[c][1] = A0*B1 + A1*B0;
        sV[c][2] = A0*B2 + A2*B0;
        sV[c][3] = A0*B3 + A3*B0;
        sV[c][4] = A1*B1;
        sV[c][5] = A1*B2 + A2*B1;
        sV[c][6] = A1*B3 + A3*B1;
        sV[c][7] = A2*B2;
        sV[c][8] = A2*B3 + A3*B2;
        sV[c][9] = A3*B3;
    }

    float qa[10], qb[10];
    #pragma unroll
    for (int p = 0; p < 10; ++p) { qa[p] = 0.f; qb[p] = 0.f; }
    for (int k0 = 0; k0 < CC; k0 += 16) {
        __syncthreads();
        for (int i = t; i < CC * 16; i += 256) {
            int r = i >> 4, kk = i & 15;
            sWa[r][kk] = Wa2[r * CC + k0 + kk];
            sWb[r][kk] = Wb2[r * CC + k0 + kk];
        }
        __syncthreads();
        if (half == 0) {
            #pragma unroll 4
            for (int kk = 0; kk < 16; ++kk) {
                int k = k0 + kk;
                float wa = sWa[c][kk], wb = sWb[c][kk];
                #pragma unroll
                for (int p = 0; p < 10; ++p) {
                    float vv = sV[k][p];
                    qa[p] = fmaf(wa, vv, qa[p]);
                    qb[p] = fmaf(wb, vv, qb[p]);
                }
            }
        }
    }
    __syncthreads();
    if (half == 0) {
        qa[9] += ba2[c];
        qb[9] += bb2[c];
        #pragma unroll
        for (int j = 0; j < 35; ++j) sE[c][j] = 0.f;
        const int pk[10] = {50, 30, 26, 25, 10, 6, 5, 2, 1, 0};
        #pragma unroll
        for (int p = 0; p < 10; ++p) {
            float va = qa[p];
            #pragma unroll
            for (int q = 0; q < 10; ++q)
                sE[c][sLUT[pk[p] + pk[q]]] += va * qb[q];
        }
    }

    float pa[18], pb[18];
    #pragma unroll
    for (int j = 0; j < 18; ++j) { pa[j] = 0.f; pb[j] = 0.f; }
    for (int k0 = 0; k0 < CC; k0 += 16) {
        __syncthreads();
        for (int i = t; i < CC * 16; i += 256) {
            int r = i >> 4, kk = i & 15;
            sWa[r][kk] = Wa3[r * CC + k0 + kk];
            sWb[r][kk] = Wb3[r * CC + k0 + kk];
        }
        __syncthreads();
        #pragma unroll 2
        for (int kk = 0; kk < 16; ++kk) {
            float wa = sWa[c][kk], wb = sWb[c][kk];
            const float* e = &sE[k0 + kk][0];
            if (half == 0) {
                #pragma unroll
                for (int j = 0; j < 18; ++j) {
                    pa[j] = fmaf(wa, e[j], pa[j]);
                    pb[j] = fmaf(wb, e[j], pb[j]);
                }
            } else {
                #pragma unroll
                for (int j = 0; j < 17; ++j) {
                    pa[j] = fmaf(wa, e[18 + j], pa[j]);
                    pb[j] = fmaf(wb, e[18 + j], pb[j]);
                }
            }
        }
    }
    if (half == 0) {
        pa[0] += ba3[c];
        pb[0] += bb3[c];
        #pragma unroll
        for (int j = 0; j < 18; ++j) {
            g_P[0][j][c] = pa[j];
            g_P[1][j][c] = pb[j];
        }
    } else {
        #pragma unroll
        for (int j = 0; j < 17; ++j) {
            g_P[0][18 + j][c] = pa[j];
            g_P[1][18 + j][c] = pb[j];
        }
    }
}

// ---------------------------------------------------------------------------
// Main: one CTA per m (full n-range, 6 internal tiles). Thread = channel.
// Prologue folds u^b into coefficients (35 -> 15 monomials in (d,v)), packs
// into f32x2 with log2(e) pre-folded into P_a. Hot loop: packed poly eval +
// dual online softmax over pairs of n. Epilogue normalizes and writes g_norm.
// ---------------------------------------------------------------------------
__global__ void __launch_bounds__(128) fps_main_kernel(const float* __restrict__ x)
{
    // interleaved monomials: [pair nn][slot 0..13, pad to 18][even/odd]
    __shared__ __align__(16) float smP[TILE/2][18][2];
    __shared__ __align__(16) float smX[3][TILE];
    const int m = blockIdx.x;
    const int t = threadIdx.x;

    const float xm0 = x[3*m], xm1 = x[3*m+1], xm2 = x[3*m+2];
    const float um2 = fmaf(xm0, xm0, fmaf(xm1, xm1, xm2 * xm2));
    const float u = sqrtf(um2);

    // ---- prologue: fold u^b into coefficients, pack duplicated f32x2 ----
    float up[5];
    up[0] = 1.f; up[1] = u; up[2] = um2; up[3] = um2 * u; up[4] = um2 * um2;
    const int JB[35] = {0,0,0,0,0, 1,1,1,1, 2,2,2, 3,3, 4,
                        0,0,0,0, 1,1,1, 2,2, 3,
                        0,0,0, 1,1, 2,
                        0,0, 1, 0};
    const int JF[35] = {0,1,2,3,4, 0,1,2,3, 0,1,2, 0,1, 0,
                        5,6,7,8, 5,6,7, 5,6, 5,
                        9,10,11, 9,10, 9,
                        12,13, 12, 14};
    float paf[15], pbf[15];
    #pragma unroll
    for (int f = 0; f < 15; ++f) { paf[f] = 0.f; pbf[f] = 0.f; }
    #pragma unroll
    for (int j = 0; j < 35; ++j) {
        float ub = up[JB[j]];
        paf[JF[j]] = fmaf(g_P[0][j][t], ub, paf[JF[j]]);
        pbf[JF[j]] = fmaf(g_P[1][j][t], ub, pbf[JF[j]]);
    }
    ull paf2[15], pbf2[15];
    #pragma unroll
    for (int j = 0; j < 15; ++j) {
        float a = paf[j] * L2E;              // fold log2(e) into P_a
        paf2[j] = pack2(a, a);
        pbf2[j] = pack2(pbf[j], pbf[j]);
    }

    float Mx0 = -1e30f, Mx1 = -1e30f;
    ull D2 = pack2(0.f, 0.f);
    ull A0 = D2, A1 = D2, A2 = D2;

    for (int tile = 0; tile < NTILES; ++tile) {
        // ---- phase 1: monomials of (d, v) for this tile's 128 n's ----
        {
            const int n = tile * TILE + t;
            float xn0 = x[3*n], xn1 = x[3*n+1], xn2 = x[3*n+2];
            float vn2 = fmaf(xn0, xn0, fmaf(xn1, xn1, xn2 * xn2));
            float v = sqrtf(vn2);
            float d2 = um2 + vn2 - 2.f * fmaf(xm0, xn0, fmaf(xm1, xn1, xm2 * xn2));
            float d = sqrtf(fmaxf(d2, 0.f));
            float v2 = v * v, v3 = v2 * v, v4 = v2 * v2;
            float dd2 = d * d, dd3 = dd2 * d, dd4 = dd2 * dd2;
            __syncthreads();     // previous tile's readers are done
            const int pr = t >> 1, ln = t & 1;
            smP[pr][0][ln]  = v;      smP[pr][1][ln]  = v2;
            smP[pr][2][ln]  = v3;     smP[pr][3][ln]  = v4;
            smP[pr][4][ln]  = d;      smP[pr][5][ln]  = d*v;
            smP[pr][6][ln]  = d*v2;   smP[pr][7][ln]  = d*v3;
            smP[pr][8][ln]  = dd2;    smP[pr][9][ln]  = dd2*v;
            smP[pr][10][ln] = dd2*v2; smP[pr][11][ln] = dd3;
            smP[pr][12][ln] = dd3*v;  smP[pr][13][ln] = dd4;
            smX[0][t] = xn0; smX[1][t] = xn1; smX[2][t] = xn2;
            __syncthreads();
        }

        // ---- phase 2: packed poly eval + dual online softmax ----
        #pragma unroll 2
        for (int nn = 0; nn < TILE / 2; ++nn) {
            ull la = paf2[0], lb = pbf2[0];
            #pragma unroll
            for (int sj = 0; sj < 14; sj += 2) {
                ulonglong2 q = *(const ulonglong2*)&smP[nn][sj][0];
                la = ffma2(paf2[sj + 1], q.x, la);
                lb = ffma2(pbf2[sj + 1], q.x, lb);
                la = ffma2(paf2[sj + 2], q.y, la);
                lb = ffma2(pbf2[sj + 2], q.y, lb);
            }
            ull h2 = fmul2(la, lb);          // log2 units
            float hlo, hhi;
            unpack2(hlo, hhi, h2);

            if (hlo > Mx0 || hhi > Mx1) {    // rare rescale
                float nM0 = fmaxf(Mx0, hlo), nM1 = fmaxf(Mx1, hhi);
                float r0 = exp2f(Mx0 - nM0), r1 = exp2f(Mx1 - nM1);
                Mx0 = nM0; Mx1 = nM1;
                ull r2 = pack2(r0, r1);
                D2 = fmul2(D2, r2);
                A0 = fmul2(A0, r2); A1 = fmul2(A1, r2); A2 = fmul2(A2, r2);
            }
            float e0 = exp2f(hlo - Mx0), e1 = exp2f(hhi - Mx1);
            ull e2 = pack2(e0, e1);
            D2 = fadd2(D2, e2);
            A0 = ffma2(e2, *(const ull*)&smX[0][2*nn], A0);
            A1 = ffma2(e2, *(const ull*)&smX[1][2*nn], A1);
            A2 = ffma2(e2, *(const ull*)&smX[2][2*nn], A2);
        }
    }

    // ---- epilogue: merge even/odd lanes, normalize, write ----
    float D0, D1, a00, a10, a01, a11, a02, a12;
    unpack2(D0, D1, D2);
    unpack2(a00, a10, A0);
    unpack2(a01, a11, A1);
    unpack2(a02, a12, A2);
    float Mx = fmaxf(Mx0, Mx1);
    float r0 = exp2f(Mx0 - Mx);
    float r1 = exp2f(Mx1 - Mx);
    float inv = 1.f / fmaf(D0, r0, D1 * r1);
    g_norm[0][m][t] = fmaf(a00, r0, a10 * r1) * inv;
    g_norm[1][m][t] = fmaf(a01, r0, a11 * r1) * inv;
    g_norm[2][m][t] = fmaf(a02, r0, a12 * r1) * inv;
}

// ---------------------------------------------------------------------------
// ReduceB: sum g_norm over a 16-m block, apply Wf, tree-reduce over channels,
// emit 6 partial scalars per block. grid=RBLK, block=128. Deterministic.
// ---------------------------------------------------------------------------
__global__ void __launch_bounds__(128) reduceB_kernel(const float* __restrict__ Wf)
{
    __shared__ float red[6][CC];
    const int c = threadIdx.x;
    const int m0 = blockIdx.x * (NP / RBLK);
    float s0 = 0.f, s1 = 0.f, s2 = 0.f;
    #pragma unroll
    for (int mi = 0; mi < NP / RBLK; ++mi) {
        s0 += g_norm[0][m0 + mi][c];
        s1 += g_norm[1][m0 + mi][c];
        s2 += g_norm[2][m0 + mi][c];
    }
    float w0 = Wf[c], w1 = Wf[CC + c];
    red[0][c] = w0 * s0; red[1][c] = w0 * s1; red[2][c] = w0 * s2;
    red[3][c] = w1 * s0; red[4][c] = w1 * s1; red[5][c] = w1 * s2;
    __syncthreads();
    for (int off = 64; off > 0; off >>= 1) {
        if (c < off) {
            #pragma unroll
            for (int q = 0; q < 6; ++q) red[q][c] += red[q][c + off];
        }
        __syncthreads();
    }
    if (c < 6) g_fin[blockIdx.x][c] = red[c][0];
}

// ---------------------------------------------------------------------------
// ReduceC: one warp folds the 48x6 partials and emits the 9 output floats.
// ---------------------------------------------------------------------------
__global__ void __launch_bounds__(32) reduceC_kernel(const float* __restrict__ x,
                                                     float* __restrict__ out)
{
    const int l = threadIdx.x;
    float acc[6];
    #pragma unroll
    for (int q = 0; q < 6; ++q) {
        float v = g_fin[l][q];               // lanes 0..31
        if (l < RBLK - 32) v += g_fin[l + 32][q];
        acc[q] = v;
    }
    #pragma unroll
    for (int off = 16; off > 0; off >>= 1) {
        #pragma unroll
        for (int q = 0; q < 6; ++q)
            acc[q] += __shfl_xor_sync(0xffffffffu, acc[q], off);
    }
    if (l < 3) out[l] = x[l];                // row 0 = x[0, 0, :]
    if (l == 0) {
        #pragma unroll
        for (int q = 0; q < 6; ++q) out[3 + q] = acc[q];
    }
}

extern "C" void kernel_launch(void* const* d_in, const int* in_sizes, int n_in,
                              void* d_out, int out_size)
{
    const float* x   = (const float*)d_in[0];
    const float* Wa1 = (const float*)d_in[1];
    const float* ba1 = (const float*)d_in[2];
    const float* Wb1 = (const float*)d_in[3];
    const float* bb1 = (const float*)d_in[4];
    const float* Wa2 = (const float*)d_in[5];
    const float* ba2 = (const float*)d_in[6];
    const float* Wb2 = (const float*)d_in[7];
    const float* bb2 = (const float*)d_in[8];
    const float* Wa3 = (const float*)d_in[9];
    const float* ba3 = (const float*)d_in[10];
    const float* Wb3 = (const float*)d_in[11];
    const float* bb3 = (const float*)d_in[12];
    const float* Wf  = (const float*)d_in[13];

    precompute_kernel<<<1, 256>>>(Wa1, ba1, Wb1, bb1,
                                  Wa2, ba2, Wb2, bb2,
                                  Wa3, ba3, Wb3, bb3);
    fps_main_kernel<<<NP, 128>>>(x);
    reduceB_kernel<<<RBLK, 128>>>(Wf);
    reduceC_kernel<<<1, 32>>>(x, (float*)d_out);
}

// round 11
// speedup vs baseline: 2.7057x; 1.0500x over previous
#include <cuda_runtime.h>

#define NP 768
#define CC 128
#define TILE 128
#define NTILES (NP / TILE)    // 6 n-tiles per CTA
#define L2E 1.4426950408889634f

// Quartic polynomial coefficients (from precompute): [o][monomial j][channel]
__device__ float g_P[2][35][CC];
// Normalized per-(m,c) softmax aggregates: [q in 0..2][m][c]
__device__ float g_norm[3][NP][CC];

// ---------------- f32x2 packed helpers (sm_103a) ----------------
typedef unsigned long long ull;
__device__ __forceinline__ ull pack2(float lo, float hi) {
    ull r;
    asm("mov.b64 %0, {%1,%2};" : "=l"(r) : "f"(lo), "f"(hi));
    return r;
}
__device__ __forceinline__ void unpack2(float& lo, float& hi, ull v) {
    asm("mov.b64 {%0,%1}, %2;" : "=f"(lo), "=f"(hi) : "l"(v));
}
__device__ __forceinline__ ull ffma2(ull a, ull b, ull c) {
    ull d;
    asm("fma.rn.f32x2 %0, %1, %2, %3;" : "=l"(d) : "l"(a), "l"(b), "l"(c));
    return d;
}
__device__ __forceinline__ ull fmul2(ull a, ull b) {
    ull d;
    asm("mul.rn.f32x2 %0, %1, %2;" : "=l"(d) : "l"(a), "l"(b));
    return d;
}
__device__ __forceinline__ ull fadd2(ull a, ull b) {
    ull d;
    asm("add.rn.f32x2 %0, %1, %2;" : "=l"(d) : "l"(a), "l"(b));
    return d;
}
// bare hardware exp2 (no libdevice fixups)
__device__ __forceinline__ float ex2(float x) {
    float y;
    asm("ex2.approx.ftz.f32 %0, %1;" : "=f"(y) : "f"(x));
    return y;
}

// ---------------------------------------------------------------------------
// Precompute: expand the 3 bilinear layers into per-channel quartic
// polynomials in (d, u, v). One CTA, 256 threads.
// Monomials (35): a=0..4 (d), b=0..4-a (u), c=0..4-a-b (v), lexicographic.
// ---------------------------------------------------------------------------
__global__ void __launch_bounds__(256) precompute_kernel(
    const float* __restrict__ Wa1, const float* __restrict__ ba1,
    const float* __restrict__ Wb1, const float* __restrict__ bb1,
    const float* __restrict__ Wa2, const float* __restrict__ ba2,
    const float* __restrict__ Wb2, const float* __restrict__ bb2,
    const float* __restrict__ Wa3, const float* __restrict__ ba3,
    const float* __restrict__ Wb3, const float* __restrict__ bb3)
{
    __shared__ float sV[CC][10];
    __shared__ float sE[CC][35];
    __shared__ float sWa[CC][17], sWb[CC][17];
    __shared__ int sLUT[125];
    const int t = threadIdx.x;
    const int c = t & 127;
    const int half = t >> 7;

    if (t == 0) {
        int j = 0;
        for (int a = 0; a <= 4; ++a)
            for (int b = 0; b <= 4 - a; ++b)
                for (int cc = 0; cc <= 4 - a - b; ++cc)
                    sLUT[a * 25 + b * 5 + cc] = j++;
    }
    if (half == 0) {
        float A0 = Wa1[3*c], A1 = Wa1[3*c+1], A2 = Wa1[3*c+2], A3 = ba1[c];
        float B0 = Wb1[3*c], B1 = Wb1[3*c+1], B2 = Wb1[3*c+2], B3 = bb1[c];
        sV[c][0] = A0*B0;
        sV[c][1] = A0*B1 + A1*B0;
        sV[c][2] = A0*B2 + A2*B0;
        sV[c][3] = A0*B3 + A3*B0;
        sV[c][4] = A1*B1;
        sV[c][5] = A1*B2 + A2*B1;
        sV[c][6] = A1*B3 + A3*B1;
        sV[c][7] = A2*B2;
        sV[c][8] = A2*B3 + A3*B2;
        sV[c][9] = A3*B3;
    }

    // ---- Layer 2: split the k-range across the two thread-halves ----
    float qa[10], qb[10];
    #pragma unroll
    for (int p = 0; p < 10; ++p) { qa[p] = 0.f; qb[p] = 0.f; }
    for (int k0 = 0; k0 < CC; k0 += 16) {
        __syncthreads();
        for (int i = t; i < CC * 16; i += 256) {
            int r = i >> 4, kk = i & 15;
            sWa[r][kk] = Wa2[r * CC + k0 + kk];
            sWb[r][kk] = Wb2[r * CC + k0 + kk];
        }
        __syncthreads();
        if ((k0 < 64) == (half == 0)) {
            #pragma unroll 4
            for (int kk = 0; kk < 16; ++kk) {
                int k = k0 + kk;
                float wa = sWa[c][kk], wb = sWb[c][kk];
                #pragma unroll
                for (int p = 0; p < 10; ++p) {
                    float vv = sV[k][p];
                    qa[p] = fmaf(wa, vv, qa[p]);
                    qb[p] = fmaf(wb, vv, qb[p]);
                }
            }
        }
    }
    // combine the two half-partials (reuse sWa/sWb staging space)
    __syncthreads();
    if (half == 1) {
        #pragma unroll
        for (int p = 0; p < 10; ++p) { sWa[c][p] = qa[p]; sWb[c][p] = qb[p]; }
    }
    __syncthreads();
    if (half == 0) {
        #pragma unroll
        for (int p = 0; p < 10; ++p) { qa[p] += sWa[c][p]; qb[p] += sWb[c][p]; }
        qa[9] += ba2[c];
        qb[9] += bb2[c];
        #pragma unroll
        for (int j = 0; j < 35; ++j) sE[c][j] = 0.f;
        const int pk[10] = {50, 30, 26, 25, 10, 6, 5, 2, 1, 0};
        #pragma unroll
        for (int p = 0; p < 10; ++p) {
            float va = qa[p];
            #pragma unroll
            for (int q = 0; q < 10; ++q)
                sE[c][sLUT[pk[p] + pk[q]]] += va * qb[q];
        }
    }

    // ---- Layer 3: P = W3 @ E; j-range split across halves ----
    float pa[18], pb[18];
    #pragma unroll
    for (int j = 0; j < 18; ++j) { pa[j] = 0.f; pb[j] = 0.f; }
    for (int k0 = 0; k0 < CC; k0 += 16) {
        __syncthreads();
        for (int i = t; i < CC * 16; i += 256) {
            int r = i >> 4, kk = i & 15;
            sWa[r][kk] = Wa3[r * CC + k0 + kk];
            sWb[r][kk] = Wb3[r * CC + k0 + kk];
        }
        __syncthreads();
        #pragma unroll 2
        for (int kk = 0; kk < 16; ++kk) {
            float wa = sWa[c][kk], wb = sWb[c][kk];
            const float* e = &sE[k0 + kk][0];
            if (half == 0) {
                #pragma unroll
                for (int j = 0; j < 18; ++j) {
                    pa[j] = fmaf(wa, e[j], pa[j]);
                    pb[j] = fmaf(wb, e[j], pb[j]);
                }
            } else {
                #pragma unroll
                for (int j = 0; j < 17; ++j) {
                    pa[j] = fmaf(wa, e[18 + j], pa[j]);
                    pb[j] = fmaf(wb, e[18 + j], pb[j]);
                }
            }
        }
    }
    if (half == 0) {
        pa[0] += ba3[c];
        pb[0] += bb3[c];
        #pragma unroll
        for (int j = 0; j < 18; ++j) {
            g_P[0][j][c] = pa[j];
            g_P[1][j][c] = pb[j];
        }
    } else {
        #pragma unroll
        for (int j = 0; j < 17; ++j) {
            g_P[0][18 + j][c] = pa[j];
            g_P[1][18 + j][c] = pb[j];
        }
    }
}

// ---------------------------------------------------------------------------
// Main: one CTA per m. Thread = channel. Branchless ALWAYS-RESCALE online
// softmax (exact): with d = h - M, q = ex2(-|d|), exactly one of {rescale r,
// new term e} equals q and the other equals 1. All ex2 args <= 0 -> no
// overflow; D >= 1 after the first step -> no 0/0.
// ---------------------------------------------------------------------------
__global__ void __launch_bounds__(128, 5) fps_main_kernel(const float* __restrict__ x)
{
    // interleaved monomials: [pair nn][slot 0..13, pad to 18][even/odd]
    __shared__ __align__(16) float smP[TILE/2][18][2];
    __shared__ __align__(16) float smX[3][TILE];
    const int m = blockIdx.x;
    const int t = threadIdx.x;

    const float xm0 = x[3*m], xm1 = x[3*m+1], xm2 = x[3*m+2];
    const float um2 = fmaf(xm0, xm0, fmaf(xm1, xm1, xm2 * xm2));
    const float u = sqrtf(um2);

    // ---- prologue: fold u^b into coefficients, pack duplicated f32x2 ----
    float up[5];
    up[0] = 1.f; up[1] = u; up[2] = um2; up[3] = um2 * u; up[4] = um2 * um2;
    const int JB[35] = {0,0,0,0,0, 1,1,1,1, 2,2,2, 3,3, 4,
                        0,0,0,0, 1,1,1, 2,2, 3,
                        0,0,0, 1,1, 2,
                        0,0, 1, 0};
    const int JF[35] = {0,1,2,3,4, 0,1,2,3, 0,1,2, 0,1, 0,
                        5,6,7,8, 5,6,7, 5,6, 5,
                        9,10,11, 9,10, 9,
                        12,13, 12, 14};
    float paf[15], pbf[15];
    #pragma unroll
    for (int f = 0; f < 15; ++f) { paf[f] = 0.f; pbf[f] = 0.f; }
    #pragma unroll
    for (int j = 0; j < 35; ++j) {
        float ub = up[JB[j]];
        paf[JF[j]] = fmaf(g_P[0][j][t], ub, paf[JF[j]]);
        pbf[JF[j]] = fmaf(g_P[1][j][t], ub, pbf[JF[j]]);
    }
    ull paf2[15], pbf2[15];
    #pragma unroll
    for (int j = 0; j < 15; ++j) {
        float a = paf[j] * L2E;              // fold log2(e) into P_a
        paf2[j] = pack2(a, a);
        pbf2[j] = pack2(pbf[j], pbf[j]);
    }

    // ---- phase 1 for tile 0 ----
    {
        const int n = t;
        float xn0 = x[3*n], xn1 = x[3*n+1], xn2 = x[3*n+2];
        float vn2 = fmaf(xn0, xn0, fmaf(xn1, xn1, xn2 * xn2));
        float v = sqrtf(vn2);
        float d2 = um2 + vn2 - 2.f * fmaf(xm0, xn0, fmaf(xm1, xn1, xm2 * xn2));
        float d = sqrtf(fmaxf(d2, 0.f));
        float v2 = v * v, v3 = v2 * v, v4 = v2 * v2;
        float dd2 = d * d, dd3 = dd2 * d, dd4 = dd2 * dd2;
        const int pr = t >> 1, ln = t & 1;
        smP[pr][0][ln]  = v;      smP[pr][1][ln]  = v2;
        smP[pr][2][ln]  = v3;     smP[pr][3][ln]  = v4;
        smP[pr][4][ln]  = d;      smP[pr][5][ln]  = d*v;
        smP[pr][6][ln]  = d*v2;   smP[pr][7][ln]  = d*v3;
        smP[pr][8][ln]  = dd2;    smP[pr][9][ln]  = dd2*v;
        smP[pr][10][ln] = dd2*v2; smP[pr][11][ln] = dd3;
        smP[pr][12][ln] = dd3*v;  smP[pr][13][ln] = dd4;
        smX[0][t] = xn0; smX[1][t] = xn1; smX[2][t] = xn2;
        __syncthreads();
    }

    float M0 = -1e30f, M1 = -1e30f;
    ull D2 = pack2(0.f, 0.f);
    ull A0 = D2, A1 = D2, A2 = D2;

    for (int tile = 0; tile < NTILES; ++tile) {
        // ---- phase 2: packed poly eval + branchless exact online softmax ----
        #pragma unroll 2
        for (int nn = 0; nn < TILE / 2; ++nn) {
            ull la = paf2[0], lb = pbf2[0];
            #pragma unroll
            for (int sj = 0; sj < 14; sj += 2) {
                ulonglong2 q = *(const ulonglong2*)&smP[nn][sj][0];
                la = ffma2(paf2[sj + 1], q.x, la);
                lb = ffma2(pbf2[sj + 1], q.x, lb);
                la = ffma2(paf2[sj + 2], q.y, la);
                lb = ffma2(pbf2[sj + 2], q.y, lb);
            }
            ull h2 = fmul2(la, lb);          // log2 units
            float h0, h1;
            unpack2(h0, h1, h2);

            float dd0 = h0 - M0, dd1 = h1 - M1;
            float q0 = ex2(-fabsf(dd0)), q1 = ex2(-fabsf(dd1));
            bool g0 = dd0 > 0.f, g1 = dd1 > 0.f;
            float r0 = g0 ? q0 : 1.f, e0 = g0 ? 1.f : q0;
            float r1 = g1 ? q1 : 1.f, e1 = g1 ? 1.f : q1;
            M0 = fmaxf(M0, h0);
            M1 = fmaxf(M1, h1);
            ull r2 = pack2(r0, r1), e2 = pack2(e0, e1);
            D2 = ffma2(D2, r2, e2);
            A0 = ffma2(A0, r2, fmul2(e2, *(const ull*)&smX[0][2*nn]));
            A1 = ffma2(A1, r2, fmul2(e2, *(const ull*)&smX[1][2*nn]));
            A2 = ffma2(A2, r2, fmul2(e2, *(const ull*)&smX[2][2*nn]));
        }

        // ---- phase 1 for next tile ----
        if (tile + 1 < NTILES) {
            const int n = (tile + 1) * TILE + t;
            float xn0 = x[3*n], xn1 = x[3*n+1], xn2 = x[3*n+2];
            float vn2 = fmaf(xn0, xn0, fmaf(xn1, xn1, xn2 * xn2));
            float v = sqrtf(vn2);
            float d2 = um2 + vn2 - 2.f * fmaf(xm0, xn0, fmaf(xm1, xn1, xm2 * xn2));
            float d = sqrtf(fmaxf(d2, 0.f));
            float v2 = v * v, v3 = v2 * v, v4 = v2 * v2;
            float dd2 = d * d, dd3 = dd2 * d, dd4 = dd2 * dd2;
            __syncthreads();     // this tile's readers are done
            const int pr = t >> 1, ln = t & 1;
            smP[pr][0][ln]  = v;      smP[pr][1][ln]  = v2;
            smP[pr][2][ln]  = v3;     smP[pr][3][ln]  = v4;
            smP[pr][4][ln]  = d;      smP[pr][5][ln]  = d*v;
            smP[pr][6][ln]  = d*v2;   smP[pr][7][ln]  = d*v3;
            smP[pr][8][ln]  = dd2;    smP[pr][9][ln]  = dd2*v;
            smP[pr][10][ln] = dd2*v2; smP[pr][11][ln] = dd3;
            smP[pr][12][ln] = dd3*v;  smP[pr][13][ln] = dd4;
            smX[0][t] = xn0; smX[1][t] = xn1; smX[2][t] = xn2;
            __syncthreads();
        }
    }

    // ---- epilogue: merge even/odd lanes (different M), normalize, write ----
    float D0, D1, a00, a10, a01, a11, a02, a12;
    unpack2(D0, D1, D2);
    unpack2(a00, a10, A0);
    unpack2(a01, a11, A1);
    unpack2(a02, a12, A2);
    float Mm = fmaxf(M0, M1);
    float r0 = ex2(M0 - Mm);
    float r1 = ex2(M1 - Mm);
    float inv = 1.f / fmaf(D0, r0, D1 * r1);
    g_norm[0][m][t] = fmaf(a00, r0, a10 * r1) * inv;
    g_norm[1][m][t] = fmaf(a01, r0, a11 * r1) * inv;
    g_norm[2][m][t] = fmaf(a02, r0, a12 * r1) * inv;
}

// ---------------------------------------------------------------------------
// Reduce: single CTA, 1024 threads (8 m-slices x 128 channels). Sums g_norm
// over m, applies Wf, tree-reduces over channels, emits the 9 output floats.
// Deterministic fixed-order reduction.
// ---------------------------------------------------------------------------
__global__ void __launch_bounds__(1024) reduce_kernel(const float* __restrict__ x,
                                                      const float* __restrict__ Wf,
                                                      float* __restrict__ out)
{
    __shared__ float sh[3][8][CC];
    __shared__ float red[6][CC];
    const int c = threadIdx.x & 127;
    const int sl = threadIdx.x >> 7;          // 0..7
    const int m0 = sl * (NP / 8);              // 96 m per slice
    float s0 = 0.f, s1 = 0.f, s2 = 0.f;
    #pragma unroll 4
    for (int mi = 0; mi < NP / 8; ++mi) {
        s0 += g_norm[0][m0 + mi][c];
        s1 += g_norm[1][m0 + mi][c];
        s2 += g_norm[2][m0 + mi][c];
    }
    sh[0][sl][c] = s0; sh[1][sl][c] = s1; sh[2][sl][c] = s2;
    __syncthreads();
    for (int off = 4; off > 0; off >>= 1) {
        if (sl < off) {
            #pragma unroll
            for (int q = 0; q < 3; ++q)
                sh[q][sl][c] += sh[q][sl + off][c];
        }
        __syncthreads();
    }
    if (sl == 0) {
        float w0 = Wf[c], w1 = Wf[CC + c];
        float t0 = sh[0][0][c], t1 = sh[1][0][c], t2 = sh[2][0][c];
        red[0][c] = w0 * t0; red[1][c] = w0 * t1; red[2][c] = w0 * t2;
        red[3][c] = w1 * t0; red[4][c] = w1 * t1; red[5][c] = w1 * t2;
    }
    __syncthreads();
    for (int off = 64; off > 0; off >>= 1) {
        if (sl == 0 && c < off) {
            #pragma unroll
            for (int q = 0; q < 6; ++q) red[q][c] += red[q][c + off];
        }
        __syncthreads();
    }
    if (threadIdx.x < 3) out[threadIdx.x] = x[threadIdx.x];   // row 0 = x[0,0,:]
    if (threadIdx.x == 0) {
        #pragma unroll
        for (int q = 0; q < 6; ++q) out[3 + q] = red[q][0];
    }
}

extern "C" void kernel_launch(void* const* d_in, const int* in_sizes, int n_in,
                              void* d_out, int out_size)
{
    const float* x   = (const float*)d_in[0];
    const float* Wa1 = (const float*)d_in[1];
    const float* ba1 = (const float*)d_in[2];
    const float* Wb1 = (const float*)d_in[3];
    const float* bb1 = (const float*)d_in[4];
    const float* Wa2 = (const float*)d_in[5];
    const float* ba2 = (const float*)d_in[6];
    const float* Wb2 = (const float*)d_in[7];
    const float* bb2 = (const float*)d_in[8];
    const float* Wa3 = (const float*)d_in[9];
    const float* ba3 = (const float*)d_in[10];
    const float* Wb3 = (const float*)d_in[11];
    const float* bb3 = (const float*)d_in[12];
    const float* Wf  = (const float*)d_in[13];

    precompute_kernel<<<1, 256>>>(Wa1, ba1, Wb1, bb1,
                                  Wa2, ba2, Wb2, bb2,
                                  Wa3, ba3, Wb3, bb3);
    fps_main_kernel<<<NP, 128>>>(x);
    reduce_kernel<<<1, 1024>>>(x, Wf, (float*)d_out);
}